// round 1
// baseline (speedup 1.0000x reference)
#include <cuda_runtime.h>
#include <cuda_bf16.h>

// Shapes (fixed by the problem)
#define B    4
#define LQ   128
#define LK   1024
#define DQ   512
#define DK   512
#define DV   512
#define UNITS 256

// Scratch (device globals — no allocation allowed)
__device__ float g_WTq[DQ * UNITS];            // 512 x 256
__device__ float g_WTk[DK * UNITS];            // 512 x 256
__device__ float g_qp [B * LQ * UNITS];        // 4*128*256
__device__ float g_kp [B * LK * UNITS];        // 4*1024*256
__device__ float g_attn[B * LQ * LK];          // 4*128*1024
__device__ int   g_vlen[B];

__device__ __forceinline__ float tanh_fast(float x) {
    float y;
    asm("tanh.approx.f32 %0, %1;" : "=f"(y) : "f"(x));
    return y;
}

// ---------------------------------------------------------------------------
// 0) Decode valid_len: dataset may hand us int64 or int32. Disambiguate by
//    range: values must be in [1, 1024]. int32 data read as int64 produces
//    huge numbers (low|high<<32), int64 data read as int32 produces zeros in
//    odd slots — so "all int64 reads in range" uniquely identifies int64.
// ---------------------------------------------------------------------------
__global__ void decode_vlen_kernel(const void* __restrict__ vl) {
    const long long* l = (const long long*)vl;
    const int*       w = (const int*)vl;
    bool ok64 = true;
    #pragma unroll
    for (int i = 0; i < B; i++) {
        long long x = l[i];
        if (x < 1 || x > LK) ok64 = false;
    }
    #pragma unroll
    for (int i = 0; i < B; i++) {
        g_vlen[i] = ok64 ? (int)l[i] : w[i];
    }
}

// ---------------------------------------------------------------------------
// 1) Transpose W[256][512] -> WT[512][256]  (for coalesced GEMM B-operand)
// ---------------------------------------------------------------------------
__global__ void transpose_w_kernel(const float* __restrict__ W, float* __restrict__ WT) {
    __shared__ float t[32][33];
    int bx = blockIdx.x;  // along 512 (d), 16 tiles
    int by = blockIdx.y;  // along 256 (u), 8 tiles
    int x = bx * 32 + threadIdx.x;   // d
    int y = by * 32 + threadIdx.y;   // u
    #pragma unroll
    for (int i = 0; i < 32; i += 8)
        t[threadIdx.y + i][threadIdx.x] = W[(y + i) * 512 + x];
    __syncthreads();
    int xo = by * 32 + threadIdx.x;  // u
    int yo = bx * 32 + threadIdx.y;  // d
    #pragma unroll
    for (int i = 0; i < 32; i += 8)
        WT[(yo + i) * 256 + xo] = t[threadIdx.x][threadIdx.y + i];
}

// ---------------------------------------------------------------------------
// 2) Projection GEMM: Y[M,256] = X[M,512] @ WT[512,256]
//    BM=64, BN=64, BK=16, 256 threads, 4x4 micro-tile.
//    M is a multiple of 64, K=512, N=256 — no bounds checks needed.
// ---------------------------------------------------------------------------
__global__ __launch_bounds__(256) void proj_gemm_kernel(
    const float* __restrict__ X, const float* __restrict__ WT, float* __restrict__ Y)
{
    __shared__ float As[16][65];  // padded: conflict-free transposed stores
    __shared__ float Bs[16][64];

    int tid = threadIdx.x;
    int ty = tid >> 4, tx = tid & 15;
    int m0 = blockIdx.x * 64;
    int n0 = blockIdx.y * 64;

    float acc[4][4] = {};

    for (int k0 = 0; k0 < 512; k0 += 16) {
        // X tile: 64(m) x 16(k)
        {
            int m  = tid >> 2;
            int kq = (tid & 3) * 4;
            float4 xv = *(const float4*)(X + (size_t)(m0 + m) * 512 + k0 + kq);
            As[kq + 0][m] = xv.x;
            As[kq + 1][m] = xv.y;
            As[kq + 2][m] = xv.z;
            As[kq + 3][m] = xv.w;
        }
        // WT tile: 16(k) x 64(n)
        {
            int kk = tid >> 4;
            int nq = (tid & 15) * 4;
            *(float4*)&Bs[kk][nq] = *(const float4*)(WT + (size_t)(k0 + kk) * 256 + n0 + nq);
        }
        __syncthreads();
        #pragma unroll
        for (int kk = 0; kk < 16; kk++) {
            float a[4], b[4];
            #pragma unroll
            for (int i = 0; i < 4; i++) a[i] = As[kk][ty * 4 + i];
            #pragma unroll
            for (int j = 0; j < 4; j++) b[j] = Bs[kk][tx * 4 + j];
            #pragma unroll
            for (int i = 0; i < 4; i++)
                #pragma unroll
                for (int j = 0; j < 4; j++)
                    acc[i][j] = fmaf(a[i], b[j], acc[i][j]);
        }
        __syncthreads();
    }

    #pragma unroll
    for (int i = 0; i < 4; i++) {
        float4 o = make_float4(acc[i][0], acc[i][1], acc[i][2], acc[i][3]);
        *(float4*)(Y + (size_t)(m0 + ty * 4 + i) * 256 + n0 + tx * 4) = o;
    }
}

// ---------------------------------------------------------------------------
// 3) Fused scores + mask + softmax.
//    Grid: 128 CTAs = 4 batches x 32 q-blocks of 4. 256 threads (8 warps).
//    Per warp-iteration: one k, lane owns u = lane*8 .. lane*8+7.
//    scores[b,q,k] = sum_u v[u]*tanh(qp[b,q,u]+kp[b,k,u]); k>=vlen -> -1e6,
//    with the tanh work skipped entirely for masked k.
// ---------------------------------------------------------------------------
__global__ __launch_bounds__(256) void score_softmax_kernel(const float* __restrict__ vvec)
{
    __shared__ float sc[4][LK];       // 16 KB
    __shared__ float redbuf[8];

    int b  = blockIdx.x >> 5;
    int q0 = (blockIdx.x & 31) * 4;
    int tid = threadIdx.x, lane = tid & 31, wid = tid >> 5;
    int vlen = g_vlen[b];

    // v chunk for this lane
    float vr[8];
    {
        float4 a = *(const float4*)(vvec + lane * 8);
        float4 c = *(const float4*)(vvec + lane * 8 + 4);
        vr[0]=a.x; vr[1]=a.y; vr[2]=a.z; vr[3]=a.w;
        vr[4]=c.x; vr[5]=c.y; vr[6]=c.z; vr[7]=c.w;
    }
    // qp chunks for 4 q rows
    float qv[4][8];
    #pragma unroll
    for (int qq = 0; qq < 4; qq++) {
        const float* qrow = g_qp + (size_t)((b * LQ) + q0 + qq) * UNITS + lane * 8;
        float4 a = *(const float4*)(qrow);
        float4 c = *(const float4*)(qrow + 4);
        qv[qq][0]=a.x; qv[qq][1]=a.y; qv[qq][2]=a.z; qv[qq][3]=a.w;
        qv[qq][4]=c.x; qv[qq][5]=c.y; qv[qq][6]=c.z; qv[qq][7]=c.w;
    }

    const float* kpb = g_kp + (size_t)b * LK * UNITS;

    for (int k = wid; k < LK; k += 8) {
        if (k >= vlen) {
            if (lane == 0) {
                sc[0][k] = -1e6f; sc[1][k] = -1e6f;
                sc[2][k] = -1e6f; sc[3][k] = -1e6f;
            }
            continue;
        }
        const float* krow = kpb + (size_t)k * UNITS + lane * 8;
        float4 a = *(const float4*)(krow);
        float4 c = *(const float4*)(krow + 4);
        float kv[8] = {a.x, a.y, a.z, a.w, c.x, c.y, c.z, c.w};

        float s[4] = {0.f, 0.f, 0.f, 0.f};
        #pragma unroll
        for (int j = 0; j < 8; j++) {
            #pragma unroll
            for (int qq = 0; qq < 4; qq++) {
                float t = tanh_fast(qv[qq][j] + kv[j]);
                s[qq] = fmaf(vr[j], t, s[qq]);
            }
        }
        #pragma unroll
        for (int qq = 0; qq < 4; qq++) {
            #pragma unroll
            for (int off = 16; off > 0; off >>= 1)
                s[qq] += __shfl_xor_sync(0xFFFFFFFFu, s[qq], off);
        }
        if (lane == 0) {
            sc[0][k] = s[0]; sc[1][k] = s[1];
            sc[2][k] = s[2]; sc[3][k] = s[3];
        }
    }
    __syncthreads();

    // Softmax each of 4 rows with all 256 threads
    for (int qq = 0; qq < 4; qq++) {
        float lm = -3.0e38f;
        for (int i = tid; i < LK; i += 256) lm = fmaxf(lm, sc[qq][i]);
        #pragma unroll
        for (int off = 16; off > 0; off >>= 1)
            lm = fmaxf(lm, __shfl_xor_sync(0xFFFFFFFFu, lm, off));
        if (lane == 0) redbuf[wid] = lm;
        __syncthreads();
        float m = redbuf[0];
        #pragma unroll
        for (int w = 1; w < 8; w++) m = fmaxf(m, redbuf[w]);
        __syncthreads();

        float ls = 0.f;
        for (int i = tid; i < LK; i += 256) {
            float e = __expf(sc[qq][i] - m);
            sc[qq][i] = e;
            ls += e;
        }
        #pragma unroll
        for (int off = 16; off > 0; off >>= 1)
            ls += __shfl_xor_sync(0xFFFFFFFFu, ls, off);
        if (lane == 0) redbuf[wid] = ls;
        __syncthreads();
        float sum = 0.f;
        #pragma unroll
        for (int w = 0; w < 8; w++) sum += redbuf[w];
        float inv = 1.0f / sum;

        float* arow = g_attn + (size_t)((b * LQ) + q0 + qq) * LK;
        for (int i = tid; i < LK; i += 256) arow[i] = sc[qq][i] * inv;
        __syncthreads();
    }
}

// ---------------------------------------------------------------------------
// 4) Output GEMM: out[b] (128x512) = attn[b] (128x1024) @ value[b] (1024x512)
//    BM=32, BN=64, BK=32, 256 threads, 2x4 micro-tile. K-loop bounded by
//    ceil(vlen/32)*32 (attn is exactly 0 beyond vlen).
// ---------------------------------------------------------------------------
__global__ __launch_bounds__(256) void out_gemm_kernel(
    const float* __restrict__ value, float* __restrict__ out)
{
    __shared__ float As[32][33];
    __shared__ float Bs[32][64];

    int b  = blockIdx.z;
    int m0 = blockIdx.x * 32;   // q
    int n0 = blockIdx.y * 64;   // v-dim
    int vlen = g_vlen[b];
    int kend = (vlen + 31) & ~31;

    const float* A = g_attn + (size_t)b * LQ * LK;
    const float* V = value  + (size_t)b * LK * DV;

    int tid = threadIdx.x;
    int ty = tid >> 4, tx = tid & 15;

    float acc[2][4] = {};

    for (int k0 = 0; k0 < kend; k0 += 32) {
        // attn tile: 32(m) x 32(k), transposed into As[k][m]
        {
            int m  = tid >> 3;
            int kq = (tid & 7) * 4;
            float4 av = *(const float4*)(A + (size_t)(m0 + m) * LK + k0 + kq);
            As[kq + 0][m] = av.x;
            As[kq + 1][m] = av.y;
            As[kq + 2][m] = av.z;
            As[kq + 3][m] = av.w;
        }
        // value tile: 32(k) x 64(n)
        {
            int kk = tid >> 3;
            int nq = (tid & 7) * 8;
            const float4* src = (const float4*)(V + (size_t)(k0 + kk) * DV + n0 + nq);
            *(float4*)&Bs[kk][nq]     = src[0];
            *(float4*)&Bs[kk][nq + 4] = src[1];
        }
        __syncthreads();
        #pragma unroll
        for (int kk = 0; kk < 32; kk++) {
            float a0 = As[kk][ty * 2 + 0];
            float a1 = As[kk][ty * 2 + 1];
            float4 bv = *(const float4*)&Bs[kk][tx * 4];
            acc[0][0] = fmaf(a0, bv.x, acc[0][0]);
            acc[0][1] = fmaf(a0, bv.y, acc[0][1]);
            acc[0][2] = fmaf(a0, bv.z, acc[0][2]);
            acc[0][3] = fmaf(a0, bv.w, acc[0][3]);
            acc[1][0] = fmaf(a1, bv.x, acc[1][0]);
            acc[1][1] = fmaf(a1, bv.y, acc[1][1]);
            acc[1][2] = fmaf(a1, bv.z, acc[1][2]);
            acc[1][3] = fmaf(a1, bv.w, acc[1][3]);
        }
        __syncthreads();
    }

    #pragma unroll
    for (int i = 0; i < 2; i++) {
        float4 o = make_float4(acc[i][0], acc[i][1], acc[i][2], acc[i][3]);
        *(float4*)(out + (size_t)((b * LQ) + m0 + ty * 2 + i) * DV + n0 + tx * 4) = o;
    }
}

// ---------------------------------------------------------------------------
// kernel_launch
// Inputs (metadata order): query, key, value, valid_len, W_q, W_k, v
// ---------------------------------------------------------------------------
extern "C" void kernel_launch(void* const* d_in, const int* in_sizes, int n_in,
                              void* d_out, int out_size)
{
    const float* query = (const float*)d_in[0];   // (4,128,512)
    const float* key   = (const float*)d_in[1];   // (4,1024,512)
    const float* value = (const float*)d_in[2];   // (4,1024,512)
    const void*  vlen  = d_in[3];                 // (4,) int64 or int32
    const float* W_q   = (const float*)d_in[4];   // (256,512)
    const float* W_k   = (const float*)d_in[5];   // (256,512)
    const float* vvec  = (const float*)d_in[6];   // (256,)
    float* out = (float*)d_out;                   // (4,128,512)

    float* wtq; cudaGetSymbolAddress((void**)&wtq, g_WTq);
    float* wtk; cudaGetSymbolAddress((void**)&wtk, g_WTk);
    float* qp;  cudaGetSymbolAddress((void**)&qp,  g_qp);
    float* kp;  cudaGetSymbolAddress((void**)&kp,  g_kp);

    decode_vlen_kernel<<<1, 1>>>(vlen);

    dim3 tb(32, 8);
    dim3 tg(16, 8);
    transpose_w_kernel<<<tg, tb>>>(W_q, wtq);
    transpose_w_kernel<<<tg, tb>>>(W_k, wtk);

    // q projection: M = 4*128 = 512
    proj_gemm_kernel<<<dim3(512 / 64, 256 / 64), 256>>>(query, wtq, qp);
    // k projection: M = 4*1024 = 4096
    proj_gemm_kernel<<<dim3(4096 / 64, 256 / 64), 256>>>(key, wtk, kp);

    score_softmax_kernel<<<128, 256>>>(vvec);

    out_gemm_kernel<<<dim3(LQ / 32, DV / 64, B), 256>>>(value, out);
}

// round 2
// speedup vs baseline: 1.3767x; 1.3767x over previous
#include <cuda_runtime.h>
#include <cuda_bf16.h>

#define B     4
#define LQ    128
#define LK    1024
#define D     512
#define DV    512
#define UNITS 256

typedef unsigned long long ull;

// Scratch (device globals — no allocation allowed)
__device__ float g_qp[B * LQ * UNITS];
__device__ float g_kp[B * LK * UNITS];
__device__ float g_sc[B * LQ * LK];     // raw scores (unmasked region only)
__device__ int   g_vlen[B];

__device__ __forceinline__ float tanh_fast(float x) {
    float y;
    asm("tanh.approx.f32 %0, %1;" : "=f"(y) : "f"(x));
    return y;
}

// packed f32x2 FMA (sm_10x: 2x fp32 FMA throughput, only via PTX)
__device__ __forceinline__ ull ffma2(ull a, ull b, ull c) {
    ull d;
    asm("fma.rn.f32x2 %0, %1, %2, %3;" : "=l"(d) : "l"(a), "l"(b), "l"(c));
    return d;
}
__device__ __forceinline__ ull pack2(float x, float y) {
    ull r;
    asm("mov.b64 %0, {%1, %2};" : "=l"(r) : "f"(x), "f"(y));
    return r;
}
__device__ __forceinline__ float2 unpack2(ull v) {
    float2 f;
    asm("mov.b64 {%0, %1}, %2;" : "=f"(f.x), "=f"(f.y) : "l"(v));
    return f;
}

// ---------------------------------------------------------------------------
// 1) Fused projection GEMM for q AND k:
//    rows [0,512)  : g_qp = query @ W_q^T
//    rows [512,4608): g_kp = key  @ W_k^T
//    BM=64, BN=128, BK=16, 256 threads, 4x8 microtile via FFMA2.
//    W transposed in shared on load (no separate transpose kernel).
//    Block (0,0) thread 0 also decodes valid_len.
// ---------------------------------------------------------------------------
__global__ __launch_bounds__(256) void proj_kernel(
    const float* __restrict__ query, const float* __restrict__ key,
    const float* __restrict__ Wq,    const float* __restrict__ Wk,
    const void*  __restrict__ vl)
{
    if (blockIdx.x == 0 && blockIdx.y == 0 && threadIdx.x == 0) {
        const long long* l = (const long long*)vl;
        const int*       w = (const int*)vl;
        bool ok64 = true;
        #pragma unroll
        for (int i = 0; i < B; i++) {
            long long x = l[i];
            if (x < 1 || x > LK) ok64 = false;
        }
        #pragma unroll
        for (int i = 0; i < B; i++) g_vlen[i] = ok64 ? (int)l[i] : w[i];
    }

    __shared__ float As[16][68];    // X^T tile (pad 68: 16B-aligned rows)
    __shared__ float Bs[16][128];   // W^T tile

    int tid = threadIdx.x;
    int ty  = tid >> 4;             // 0..15 -> rows ty*4
    int tx  = tid & 15;             // 0..15 -> cols tx*8

    int mg = blockIdx.x * 64;       // global row in [0, 4608)
    int n0 = blockIdx.y * 128;

    const float *X, *W;
    float* Y;
    int m0;
    if (mg < B * LQ) { X = query; W = Wq; Y = g_qp; m0 = mg; }
    else             { X = key;   W = Wk; Y = g_kp; m0 = mg - B * LQ; }

    ull acc[4][4] = {};

    int lm = tid >> 2;              // As: row 0..63
    int lk = (tid & 3) * 4;         // As: k 0,4,8,12
    int wn = tid >> 1;              // Bs: n 0..127
    int wk = (tid & 1) * 8;         // Bs: k 0 or 8

    for (int k0 = 0; k0 < D; k0 += 16) {
        float4 xv = *(const float4*)(X + (size_t)(m0 + lm) * D + k0 + lk);
        As[lk + 0][lm] = xv.x;
        As[lk + 1][lm] = xv.y;
        As[lk + 2][lm] = xv.z;
        As[lk + 3][lm] = xv.w;

        const float* wrow = W + (size_t)(n0 + wn) * D + k0 + wk;
        float4 w0 = *(const float4*)(wrow);
        float4 w1 = *(const float4*)(wrow + 4);
        Bs[wk + 0][wn] = w0.x;
        Bs[wk + 1][wn] = w0.y;
        Bs[wk + 2][wn] = w0.z;
        Bs[wk + 3][wn] = w0.w;
        Bs[wk + 4][wn] = w1.x;
        Bs[wk + 5][wn] = w1.y;
        Bs[wk + 6][wn] = w1.z;
        Bs[wk + 7][wn] = w1.w;
        __syncthreads();

        #pragma unroll
        for (int kk = 0; kk < 16; kk++) {
            float4 av = *(const float4*)&As[kk][ty * 4];
            ull aa[4];
            aa[0] = pack2(av.x, av.x);
            aa[1] = pack2(av.y, av.y);
            aa[2] = pack2(av.z, av.z);
            aa[3] = pack2(av.w, av.w);
            longlong2 b0 = *(const longlong2*)&Bs[kk][tx * 8];
            longlong2 b1 = *(const longlong2*)&Bs[kk][tx * 8 + 4];
            ull bb[4] = {(ull)b0.x, (ull)b0.y, (ull)b1.x, (ull)b1.y};
            #pragma unroll
            for (int i = 0; i < 4; i++)
                #pragma unroll
                for (int j = 0; j < 4; j++)
                    acc[i][j] = ffma2(aa[i], bb[j], acc[i][j]);
        }
        __syncthreads();
    }

    #pragma unroll
    for (int i = 0; i < 4; i++) {
        float* dst = Y + (size_t)(m0 + ty * 4 + i) * UNITS + n0 + tx * 8;
        float2 r0 = unpack2(acc[i][0]);
        float2 r1 = unpack2(acc[i][1]);
        float2 r2 = unpack2(acc[i][2]);
        float2 r3 = unpack2(acc[i][3]);
        *(float4*)(dst)     = make_float4(r0.x, r0.y, r1.x, r1.y);
        *(float4*)(dst + 4) = make_float4(r2.x, r2.y, r3.x, r3.y);
    }
}

// ---------------------------------------------------------------------------
// 2) Scores: grid (ktile=8, qtile=16, b=4) = 512 CTAs, 256 threads.
//    CTA: 8 q-rows x 128 k. Fully-masked k-tiles exit immediately.
//    Warp handles one k per iteration; lane owns u = lane*8..lane*8+7.
//    s[b,q,k] = sum_u v[u] * tanh(qp[b,q,u] + kp[b,k,u]).  MUFU.TANH-bound.
// ---------------------------------------------------------------------------
__global__ __launch_bounds__(256) void score_kernel(const float* __restrict__ vvec)
{
    int b    = blockIdx.z;
    int q0   = blockIdx.y * 8;
    int k0   = blockIdx.x * 128;
    int vlen = g_vlen[b];
    if (k0 >= vlen) return;
    int kmax = min(k0 + 128, vlen);

    int lane = threadIdx.x & 31;
    int wid  = threadIdx.x >> 5;

    float vr[8];
    {
        float4 a = *(const float4*)(vvec + lane * 8);
        float4 c = *(const float4*)(vvec + lane * 8 + 4);
        vr[0] = a.x; vr[1] = a.y; vr[2] = a.z; vr[3] = a.w;
        vr[4] = c.x; vr[5] = c.y; vr[6] = c.z; vr[7] = c.w;
    }
    float qv[8][8];
    #pragma unroll
    for (int qq = 0; qq < 8; qq++) {
        const float* qr = g_qp + (size_t)(b * LQ + q0 + qq) * UNITS + lane * 8;
        float4 a = *(const float4*)qr;
        float4 c = *(const float4*)(qr + 4);
        qv[qq][0] = a.x; qv[qq][1] = a.y; qv[qq][2] = a.z; qv[qq][3] = a.w;
        qv[qq][4] = c.x; qv[qq][5] = c.y; qv[qq][6] = c.z; qv[qq][7] = c.w;
    }

    const float* kpb = g_kp + (size_t)b * LK * UNITS;
    float*       scb = g_sc + (size_t)(b * LQ + q0) * LK;

    for (int k = k0 + wid; k < kmax; k += 8) {
        const float* kr = kpb + (size_t)k * UNITS + lane * 8;
        float4 ka = *(const float4*)kr;
        float4 kb = *(const float4*)(kr + 4);
        float kv[8] = {ka.x, ka.y, ka.z, ka.w, kb.x, kb.y, kb.z, kb.w};

        float s[8] = {0.f, 0.f, 0.f, 0.f, 0.f, 0.f, 0.f, 0.f};
        #pragma unroll
        for (int j = 0; j < 8; j++) {
            float kj = kv[j];
            float vj = vr[j];
            #pragma unroll
            for (int qq = 0; qq < 8; qq++)
                s[qq] = fmaf(vj, tanh_fast(qv[qq][j] + kj), s[qq]);
        }
        #pragma unroll
        for (int qq = 0; qq < 8; qq++) {
            float v = s[qq];
            #pragma unroll
            for (int off = 16; off > 0; off >>= 1)
                v += __shfl_xor_sync(0xFFFFFFFFu, v, off);
            if (lane == 0) scb[(size_t)qq * LK + k] = v;
        }
    }
}

// ---------------------------------------------------------------------------
// 3) Fused softmax + output GEMM.
//    CTA: (b, 32 q-rows, 64 v-cols). Phase 1: per-row max & 1/sum over
//    [0,vlen). Phase 2: GEMM over k<kend=ceil32(vlen), staging
//    p = exp(s - rowmax) (0 beyond vlen); 1/sum applied in epilogue.
// ---------------------------------------------------------------------------
__global__ __launch_bounds__(256) void out_kernel(
    const float* __restrict__ value, float* __restrict__ out)
{
    __shared__ float As[32][34];    // p tile transposed [k][m], pad 34
    __shared__ float Bs[32][64];    // value tile [k][n]
    __shared__ float rmax[32], rinv[32];

    int b    = blockIdx.z;
    int m0   = blockIdx.x * 32;
    int n0   = blockIdx.y * 64;
    int vlen = g_vlen[b];
    int kend = (vlen + 31) & ~31;

    const float* S = g_sc  + (size_t)(b * LQ + m0) * LK;
    const float* V = value + (size_t)b * LK * DV;

    int tid  = threadIdx.x;
    int lane = tid & 31;
    int wid  = tid >> 5;

    // Phase 1: row reductions (warp per row, 4 sweeps)
    for (int r = wid; r < 32; r += 8) {
        const float* srow = S + (size_t)r * LK;
        float m = -3.0e38f;
        for (int k = lane; k < vlen; k += 32) m = fmaxf(m, srow[k]);
        #pragma unroll
        for (int off = 16; off > 0; off >>= 1)
            m = fmaxf(m, __shfl_xor_sync(0xFFFFFFFFu, m, off));
        float s = 0.f;
        for (int k = lane; k < vlen; k += 32) s += __expf(srow[k] - m);
        #pragma unroll
        for (int off = 16; off > 0; off >>= 1)
            s += __shfl_xor_sync(0xFFFFFFFFu, s, off);
        if (lane == 0) { rmax[r] = m; rinv[r] = 1.0f / s; }
    }
    __syncthreads();

    int ty = tid >> 4, tx = tid & 15;        // rows ty*2, cols tx*4
    int am = tid >> 3, ak = (tid & 7) * 4;   // As staging
    int bk = tid >> 3, bn = (tid & 7) * 8;   // Bs staging

    ull acc[2][2] = {};

    for (int k0 = 0; k0 < kend; k0 += 32) {
        float4 sv = *(const float4*)(S + (size_t)am * LK + k0 + ak);
        float mr = rmax[am];
        int kg = k0 + ak;
        As[ak + 0][am] = (kg + 0 < vlen) ? __expf(sv.x - mr) : 0.f;
        As[ak + 1][am] = (kg + 1 < vlen) ? __expf(sv.y - mr) : 0.f;
        As[ak + 2][am] = (kg + 2 < vlen) ? __expf(sv.z - mr) : 0.f;
        As[ak + 3][am] = (kg + 3 < vlen) ? __expf(sv.w - mr) : 0.f;

        const float* vp = V + (size_t)(k0 + bk) * DV + n0 + bn;
        *(float4*)&Bs[bk][bn]     = *(const float4*)(vp);
        *(float4*)&Bs[bk][bn + 4] = *(const float4*)(vp + 4);
        __syncthreads();

        #pragma unroll
        for (int kk = 0; kk < 32; kk++) {
            float2 af = *(const float2*)&As[kk][ty * 2];
            ull ap0 = pack2(af.x, af.x);
            ull ap1 = pack2(af.y, af.y);
            longlong2 bv = *(const longlong2*)&Bs[kk][tx * 4];
            acc[0][0] = ffma2(ap0, (ull)bv.x, acc[0][0]);
            acc[0][1] = ffma2(ap0, (ull)bv.y, acc[0][1]);
            acc[1][0] = ffma2(ap1, (ull)bv.x, acc[1][0]);
            acc[1][1] = ffma2(ap1, (ull)bv.y, acc[1][1]);
        }
        __syncthreads();
    }

    #pragma unroll
    for (int i = 0; i < 2; i++) {
        int r = ty * 2 + i;
        float inv = rinv[r];
        float2 r0 = unpack2(acc[i][0]);
        float2 r1 = unpack2(acc[i][1]);
        *(float4*)(out + (size_t)(b * LQ + m0 + r) * DV + n0 + tx * 4) =
            make_float4(r0.x * inv, r0.y * inv, r1.x * inv, r1.y * inv);
    }
}

// ---------------------------------------------------------------------------
// kernel_launch — inputs: query, key, value, valid_len, W_q, W_k, v
// ---------------------------------------------------------------------------
extern "C" void kernel_launch(void* const* d_in, const int* in_sizes, int n_in,
                              void* d_out, int out_size)
{
    const float* query = (const float*)d_in[0];   // (4,128,512)
    const float* key   = (const float*)d_in[1];   // (4,1024,512)
    const float* value = (const float*)d_in[2];   // (4,1024,512)
    const void*  vlen  = d_in[3];                 // (4,) int64/int32
    const float* W_q   = (const float*)d_in[4];   // (256,512)
    const float* W_k   = (const float*)d_in[5];   // (256,512)
    const float* vvec  = (const float*)d_in[6];   // (256,)
    float* out = (float*)d_out;                   // (4,128,512)

    // 1) fused q+k projection (+ vlen decode): 72 x 2 = 144 CTAs
    proj_kernel<<<dim3((B * LQ + B * LK) / 64, UNITS / 128), 256>>>(
        query, key, W_q, W_k, vlen);

    // 2) scores: 8 x 16 x 4 = 512 CTAs (masked tiles exit)
    score_kernel<<<dim3(LK / 128, LQ / 8, B), 256>>>(vvec);

    // 3) fused softmax + output GEMM: 4 x 8 x 4 = 128 CTAs
    out_kernel<<<dim3(LQ / 32, DV / 64, B), 256>>>(value, out);
}